// round 10
// baseline (speedup 1.0000x reference)
#include <cuda_runtime.h>
#include <math.h>

// Problem constants (fixed by reference: IMG=2048, strides 8/16/32, B=2, M=128)
#define L3 65536
#define L4 16384
#define L5 4096
#define LTOT (L3 + L4 + L5)   // 86016
#define NB 2
#define NGT 128

// Warp-autonomous fused kernel: each warp owns 64 consecutive locations
// (2 per thread). No shared memory, no __syncthreads. Boxes are loaded
// coalesced (lane k reads float4s 5k..5k+4 = boxes 4k..4k+3), pruned with
// the warp's single-row y value plus an x-band test, and the surviving
// ~1-3 candidates are broadcast by shuffle.
__global__ __launch_bounds__(256) void fcos_fused(
    const float4* __restrict__ gt4,    // (B, 128, 5) viewed as float4[160/batch]
    const float* __restrict__ p3,      // (B, L3, 4)
    const float* __restrict__ p4,
    const float* __restrict__ p5,
    float* __restrict__ out)           // (B, LTOT, 9)
{
    const unsigned FULL = 0xFFFFFFFFu;
    const int tid  = threadIdx.x;
    const int lane = tid & 31;
    const int gw   = (blockIdx.x * 256 + tid) >> 5;   // global warp id
    const int wbase = gw * 64;                        // first location of warp
    const int b    = (wbase >= LTOT) ? 1 : 0;
    const int locb = wbase - b * LTOT;

    // Level selection — uniform per warp (all boundaries % 64 == 0).
    float s, lo, hi;
    const float* pred;
    int nshift, off;
    if (locb < L3) {
        s = 8.0f;  lo = 0.0f;   hi = 64.0f;
        pred = p3 + (size_t)b * L3 * 4; nshift = 8; off = 0;          // n=256
    } else if (locb < L3 + L4) {
        s = 16.0f; lo = 64.0f;  hi = 128.0f;
        pred = p4 + (size_t)b * L4 * 4; nshift = 7; off = L3;         // n=128
    } else {
        s = 32.0f; lo = 128.0f; hi = INFINITY;
        pred = p5 + (size_t)b * L5 * 4; nshift = 6; off = L3 + L4;    // n=64
    }
    const int nmask = (1 << nshift) - 1;

    const int l0   = locb - off;              // level-local warp start (64-mult)
    const int lidx = l0 + 2 * lane;           // this thread's first location
    const int row  = lidx >> nshift;
    const int colw = l0 & nmask;              // warp's first column
    const int col  = lidx & nmask;
    // Analytic coords: (k+0.5)*2^m exact in fp32 -> bitwise equal to ref.
    const float y  = ((float)row + 0.5f) * s;             // single row per warp
    const float xA = ((float)col + 0.5f) * s;
    const float xB = xA + s;
    // Warp x-band.
    const float wxlo = ((float)colw + 0.5f) * s;
    const float wxhi = wxlo + 63.0f * s;

    // Prefetch predictions (2 x LDG.128).
    const float4 pA = reinterpret_cast<const float4*>(pred)[lidx];
    const float4 pB = reinterpret_cast<const float4*>(pred)[lidx + 1];

    // ---- Load this batch's 128 boxes coalesced; lane owns boxes 4k..4k+3 ----
    const float4* g4 = gt4 + (size_t)b * (NGT * 5 / 4);   // 160 float4 per batch
    const float4 f0 = g4[lane * 5 + 0];
    const float4 f1 = g4[lane * 5 + 1];
    const float4 f2 = g4[lane * 5 + 2];
    const float4 f3 = g4[lane * 5 + 3];
    const float4 f4 = g4[lane * 5 + 4];
    // Unpack 4 boxes (x0,y0,x1,y1); class float skipped.
    float bx0[4], by0[4], bx1[4], by1[4];
    bx0[0] = f0.x; by0[0] = f0.y; bx1[0] = f0.z; by1[0] = f0.w;
    bx0[1] = f1.y; by0[1] = f1.z; bx1[1] = f1.w; by1[1] = f2.x;
    bx0[2] = f2.z; by0[2] = f2.w; bx1[2] = f3.x; by1[2] = f3.y;
    bx0[3] = f3.w; by0[3] = f4.x; bx1[3] = f4.y; by1[3] = f4.z;

    // Candidate test per owned box: valid-center window
    // x in (max(x0,x1-hi), min(x1,x0+hi)), y likewise; intersect warp band.
    bool cand[4];
    #pragma unroll
    for (int r = 0; r < 4; ++r) {
        const float xl = fmaxf(bx0[r], bx1[r] - hi), xh = fminf(bx1[r], bx0[r] + hi);
        const float yl = fmaxf(by0[r], by1[r] - hi), yh = fminf(by1[r], by0[r] + hi);
        cand[r] = (xh > xl) && (y > yl) && (y < yh) && (xl < wxhi) && (xh > wxlo);
    }

    // ---- Scan candidates via ballot + shuffle broadcast ----
    unsigned long long bestA = 0ull, bestB = 0ull;
    float4 boxA, boxB;
    #pragma unroll
    for (int r = 0; r < 4; ++r) {
        unsigned m = __ballot_sync(FULL, cand[r]);
        while (m) {
            const int src = __ffs(m) - 1;
            m &= m - 1;
            const float cx0 = __shfl_sync(FULL, bx0[r], src);
            const float cy0 = __shfl_sync(FULL, by0[r], src);
            const float cx1 = __shfl_sync(FULL, bx1[r], src);
            const float cy1 = __shfl_sync(FULL, by1[r], src);
            const int j = 4 * src + r;
            const float mmv = 1e8f - (cx1 - cx0) * (cy1 - cy0);
            // mm bits (positive, order-isomorphic) | first-index tie-break.
            const unsigned long long key =
                ((unsigned long long)__float_as_uint(mmv) << 32) |
                (unsigned)(NGT - 1 - j);
            const float t  = y - cy0;
            const float bt = cy1 - y;
            const float vmin = fminf(t, bt);
            const float vmax = fmaxf(t, bt);
            {
                const float l = xA - cx0, rr = cx1 - xA;
                const float pmin = fminf(fminf(l, rr), vmin);
                const float pmax = fmaxf(fmaxf(l, rr), vmax);
                if (pmin > 0.0f && pmax > lo && pmax < hi && key > bestA) {
                    bestA = key; boxA = make_float4(cx0, cy0, cx1, cy1);
                }
            }
            {
                const float l = xB - cx0, rr = cx1 - xB;
                const float pmin = fminf(fminf(l, rr), vmin);
                const float pmax = fmaxf(fmaxf(l, rr), vmax);
                if (pmin > 0.0f && pmax > lo && pmax < hi && key > bestB) {
                    bestB = key; boxB = make_float4(cx0, cy0, cx1, cy1);
                }
            }
        }
    }

    // ---- Finalize both locations ----
    float v[18];
    const float inv_s = 1.0f / s;

    #pragma unroll
    for (int q = 0; q < 2; ++q) {
        const unsigned long long best = q ? bestB : bestA;
        const float x = q ? xB : xA;
        const float4 bx = q ? boxB : boxA;
        float* o = v + q * 9;
        if (best == 0ull) {
            o[0] = o[1] = o[2] = o[3] = -1.0f;
            o[4] = -1.0f;
        } else {
            const float d0 = (x - bx.x) * inv_s;
            const float d1 = (y - bx.y) * inv_s;
            const float d2 = (bx.z - x) * inv_s;
            const float d3 = (bx.w - y) * inv_s;
            const float lrmin = fminf(d0, d2), lrmax = fmaxf(d0, d2);
            const float tbmin = fminf(d1, d3), tbmax = fmaxf(d1, d3);
            const float ratio = fminf(lrmin, tbmin) / (fmaxf(lrmax, tbmax) + 1e-6f);
            o[0] = d0; o[1] = d1; o[2] = d2; o[3] = d3;
            o[4] = sqrtf(fmaxf(ratio, 0.0f));
        }
        const float4 p = q ? pB : pA;
        o[5] = fmaxf(x - fmaxf(p.x, 0.0f) * s, 0.0f);
        o[6] = fmaxf(y - fmaxf(p.y, 0.0f) * s, 0.0f);
        o[7] = fmaxf(x + fmaxf(p.z, 0.0f) * s, 0.0f);
        o[8] = fmaxf(y + fmaxf(p.w, 0.0f) * s, 0.0f);
    }

    // 18 contiguous floats per thread.
    const size_t i0 = (size_t)b * LTOT + off + lidx;
    float2* o2 = reinterpret_cast<float2*>(out + i0 * 9);
    #pragma unroll
    for (int k = 0; k < 9; ++k)
        o2[k] = make_float2(v[2 * k], v[2 * k + 1]);
}

extern "C" void kernel_launch(void* const* d_in, const int* in_sizes, int n_in,
                              void* d_out, int out_size) {
    const float4* gt4 = (const float4*)d_in[3];
    const float* p3 = (const float*)d_in[4];
    const float* p4 = (const float*)d_in[5];
    const float* p5 = (const float*)d_in[6];
    float* out = (float*)d_out;

    const int blocks = NB * LTOT / 512;   // 336 blocks x 256 thr (8 indep warps)
    fcos_fused<<<blocks, 256>>>(gt4, p3, p4, p5, out);
}

// round 11
// speedup vs baseline: 1.4244x; 1.4244x over previous
#include <cuda_runtime.h>
#include <math.h>

// Problem constants (fixed by reference: IMG=2048, strides 8/16/32, B=2, M=128)
#define L3 65536
#define L4 16384
#define L5 4096
#define LTOT (L3 + L4 + L5)   // 86016
#define NB 2
#define NGT 128

// Fused kernel: 672 blocks x 128 threads, 2 locations/thread (256 locs/block).
// All level/batch boundaries are multiples of 256 -> each block is
// (batch, level)-uniform; 256 locs = 1 grid row at p3 (2 at p4, 4 at p5),
// so the block y-band is tight and the ballot-compacted shortlist is tiny.
// New in this round: output staged through shared memory so global stores
// are fully coalesced (9x fewer L1 wavefronts than direct 72B-strided AoS).
__global__ __launch_bounds__(128) void fcos_fused(
    const float* __restrict__ gt,      // (B, 128, 5)
    const float* __restrict__ p3,      // (B, L3, 4)
    const float* __restrict__ p4,
    const float* __restrict__ p5,
    float* __restrict__ out)           // (B, LTOT, 9)
{
    __shared__ float4 sbox[NGT];                 // {x0,y0,x1,y1} per slot
    __shared__ unsigned long long skey[NGT];     // packed winner key
    __shared__ int swc[4];                       // per-warp shortlist count
    __shared__ float sOut[128 * 18];             // staged output (9216 B)

    const int tid   = threadIdx.x;               // 0..127
    const int gbase = blockIdx.x * 256;
    const int b     = (gbase >= LTOT) ? 1 : 0;
    const int locb  = gbase - b * LTOT;

    // Level selection — uniform per block.
    float s, lo, hi;
    const float* pred;
    int nshift, off;
    if (locb < L3) {
        s = 8.0f;  lo = 0.0f;   hi = 64.0f;
        pred = p3 + (size_t)b * L3 * 4; nshift = 8; off = 0;          // n=256
    } else if (locb < L3 + L4) {
        s = 16.0f; lo = 64.0f;  hi = 128.0f;
        pred = p4 + (size_t)b * L4 * 4; nshift = 7; off = L3;         // n=128
    } else {
        s = 32.0f; lo = 128.0f; hi = INFINITY;
        pred = p5 + (size_t)b * L5 * 4; nshift = 6; off = L3 + L4;    // n=64
    }
    const int nmask = (1 << nshift) - 1;

    const int l0   = locb - off;             // level-local block start
    const int lidx = l0 + 2 * tid;           // this thread's first location
    const int row  = lidx >> nshift;
    const int col  = lidx & nmask;           // 2-aligned -> both in one row
    // Analytic coords: (k+0.5)*2^m exact in fp32 -> bitwise equal to ref.
    const float y  = ((float)row + 0.5f) * s;
    const float xA = ((float)col + 0.5f) * s;
    const float xB = xA + s;

    // Analytic y-band of the whole block (1/2/4 rows).
    const float ylo = ((float)(l0 >> nshift)         + 0.5f) * s;
    const float yhi = ((float)((l0 + 255) >> nshift) + 0.5f) * s;

    // Prefetch predictions (2 x LDG.128, independent of the barrier).
    const float4 pA = reinterpret_cast<const float4*>(pred)[lidx];
    const float4 pB = reinterpret_cast<const float4*>(pred)[lidx + 1];

    // ---- Phase 1: 4 warps build compacted per-warp shortlists ----
    {
        const int w    = tid >> 5;
        const int lane = tid & 31;
        const float* g = gt + ((size_t)(b * NGT + tid)) * 5;
        const float bx0 = g[0], by0 = g[1], bx1 = g[2], by1 = g[3];
        // Valid-center window: x in (max(x0,x1-hi), min(x1,x0+hi)), same in y.
        const float xl = fmaxf(bx0, bx1 - hi), xh = fminf(bx1, bx0 + hi);
        const float yl = fmaxf(by0, by1 - hi), yh = fminf(by1, by0 + hi);
        const bool cand = (xh > xl) && (yh > ylo) && (yl < yhi);
        const unsigned mask = __ballot_sync(0xFFFFFFFFu, cand);
        if (cand) {
            const int slot = (w << 5) + __popc(mask & ((1u << lane) - 1u));
            sbox[slot] = make_float4(bx0, by0, bx1, by1);
            const float mmv = 1e8f - (bx1 - bx0) * (by1 - by0);
            // mm bits (positive float, order-isomorphic) | first-index tie | slot.
            skey[slot] = ((unsigned long long)__float_as_uint(mmv) << 32) |
                         ((unsigned)(NGT - 1 - tid) << 8) | (unsigned)slot;
        }
        if (lane == 0) swc[w] = __popc(mask);
    }
    __syncthreads();

    // ---- Phase 2: scan compacted segments, 2 x-positions per entry ----
    unsigned long long bestA = 0ull, bestB = 0ull;
    #pragma unroll
    for (int w = 0; w < 4; ++w) {
        const int cnt  = swc[w];
        const int base = w << 5;
        for (int k = 0; k < cnt; ++k) {
            const float4 bx = sbox[base + k];
            const float t  = y - bx.y;
            const float bt = bx.w - y;
            const float vmin = fminf(t, bt);
            const float vmax = fmaxf(t, bt);
            const unsigned long long key = skey[base + k];
            {
                const float l = xA - bx.x, r = bx.z - xA;
                const float pmin = fminf(fminf(l, r), vmin);
                const float pmax = fmaxf(fmaxf(l, r), vmax);
                if (pmin > 0.0f && pmax > lo && pmax < hi && key > bestA)
                    bestA = key;
            }
            {
                const float l = xB - bx.x, r = bx.z - xB;
                const float pmin = fminf(fminf(l, r), vmin);
                const float pmax = fmaxf(fmaxf(l, r), vmax);
                if (pmin > 0.0f && pmax > lo && pmax < hi && key > bestB)
                    bestB = key;
            }
        }
    }

    // ---- Phase 3: finalize both locations into the smem staging buffer ----
    {
        const float inv_s = 1.0f / s;
        float* o = sOut + tid * 18;
        #pragma unroll
        for (int q = 0; q < 2; ++q, o += 9) {
            const unsigned long long best = q ? bestB : bestA;
            const float x = q ? xB : xA;
            if (best == 0ull) {
                o[0] = o[1] = o[2] = o[3] = -1.0f;
                o[4] = -1.0f;
            } else {
                const float4 bx = sbox[best & 0xFFu];
                const float d0 = (x - bx.x) * inv_s;
                const float d1 = (y - bx.y) * inv_s;
                const float d2 = (bx.z - x) * inv_s;
                const float d3 = (bx.w - y) * inv_s;
                const float lrmin = fminf(d0, d2), lrmax = fmaxf(d0, d2);
                const float tbmin = fminf(d1, d3), tbmax = fmaxf(d1, d3);
                const float ratio = fminf(lrmin, tbmin) /
                                    (fmaxf(lrmax, tbmax) + 1e-6f);
                o[0] = d0; o[1] = d1; o[2] = d2; o[3] = d3;
                o[4] = sqrtf(fmaxf(ratio, 0.0f));
            }
            const float4 p = q ? pB : pA;
            o[5] = fmaxf(x - fmaxf(p.x, 0.0f) * s, 0.0f);
            o[6] = fmaxf(y - fmaxf(p.y, 0.0f) * s, 0.0f);
            o[7] = fmaxf(x + fmaxf(p.z, 0.0f) * s, 0.0f);
            o[8] = fmaxf(y + fmaxf(p.w, 0.0f) * s, 0.0f);
        }
    }
    __syncthreads();

    // ---- Phase 4: coalesced block store (9 rounds of warp-contiguous f2) ----
    // Block's output region: 256 locs * 9 floats = 1152 float2, contiguous.
    {
        const float2* src = reinterpret_cast<const float2*>(sOut);
        float2* dst = reinterpret_cast<float2*>(
            out + ((size_t)b * LTOT + off + l0) * 9);
        #pragma unroll
        for (int k = 0; k < 9; ++k) {
            const int idx = k * 128 + tid;
            dst[idx] = src[idx];
        }
    }
}

extern "C" void kernel_launch(void* const* d_in, const int* in_sizes, int n_in,
                              void* d_out, int out_size) {
    const float* gt = (const float*)d_in[3];
    const float* p3 = (const float*)d_in[4];
    const float* p4 = (const float*)d_in[5];
    const float* p5 = (const float*)d_in[6];
    float* out = (float*)d_out;

    const int blocks = NB * LTOT / 256;   // 672
    fcos_fused<<<blocks, 128>>>(gt, p3, p4, p5, out);
}

// round 12
// speedup vs baseline: 1.4296x; 1.0037x over previous
#include <cuda_runtime.h>
#include <math.h>

// Problem constants (fixed by reference: IMG=2048, strides 8/16/32, B=2, M=128)
#define L3 65536
#define L4 16384
#define L5 4096
#define LTOT (L3 + L4 + L5)   // 86016
#define NB 2
#define NGT 128

// Fused kernel: 672 blocks x 128 threads, 2 locations/thread (256 locs/block).
// All level/batch boundaries are multiples of 256 -> each block is
// (batch, level)-uniform; 256 locs = 1 grid row at p3 (2 at p4, 4 at p5).
// This round: decode half staged before the first barrier; second block
// barrier replaced by __syncwarp (warp-local staging copy); float4 copy.
__global__ __launch_bounds__(128) void fcos_fused(
    const float* __restrict__ gt,      // (B, 128, 5)
    const float* __restrict__ p3,      // (B, L3, 4)
    const float* __restrict__ p4,
    const float* __restrict__ p5,
    float* __restrict__ out)           // (B, LTOT, 9)
{
    __shared__ float4 sbox[NGT];                 // {x0,y0,x1,y1} per slot
    __shared__ unsigned long long skey[NGT];     // packed winner key
    __shared__ int swc[4];                       // per-warp shortlist count
    __shared__ float sOut[128 * 18];             // staged output (9216 B)

    const int tid   = threadIdx.x;               // 0..127
    const int w     = tid >> 5;
    const int lane  = tid & 31;
    const int gbase = blockIdx.x * 256;
    const int b     = (gbase >= LTOT) ? 1 : 0;
    const int locb  = gbase - b * LTOT;

    // Level selection — uniform per block.
    float s, lo, hi;
    const float* pred;
    int nshift, off;
    if (locb < L3) {
        s = 8.0f;  lo = 0.0f;   hi = 64.0f;
        pred = p3 + (size_t)b * L3 * 4; nshift = 8; off = 0;          // n=256
    } else if (locb < L3 + L4) {
        s = 16.0f; lo = 64.0f;  hi = 128.0f;
        pred = p4 + (size_t)b * L4 * 4; nshift = 7; off = L3;         // n=128
    } else {
        s = 32.0f; lo = 128.0f; hi = INFINITY;
        pred = p5 + (size_t)b * L5 * 4; nshift = 6; off = L3 + L4;    // n=64
    }
    const int nmask = (1 << nshift) - 1;

    const int l0   = locb - off;             // level-local block start
    const int lidx = l0 + 2 * tid;           // this thread's first location
    const int row  = lidx >> nshift;
    const int col  = lidx & nmask;           // 2-aligned -> both in one row
    // Analytic coords: (k+0.5)*2^m exact in fp32 -> bitwise equal to ref.
    const float y  = ((float)row + 0.5f) * s;
    const float xA = ((float)col + 0.5f) * s;
    const float xB = xA + s;

    // Analytic y-band of the whole block (1/2/4 rows).
    const float ylo = ((float)(l0 >> nshift)         + 0.5f) * s;
    const float yhi = ((float)((l0 + 255) >> nshift) + 0.5f) * s;

    // gt load issued early (phase 1 consumes it).
    const float* g = gt + ((size_t)(b * NGT + tid)) * 5;
    const float bx0 = g[0], by0 = g[1], bx1 = g[2], by1 = g[3];

    // Predictions (2 x LDG.128).
    const float4 pA = reinterpret_cast<const float4*>(pred)[lidx];
    const float4 pB = reinterpret_cast<const float4*>(pred)[lidx + 1];

    // ---- Stage the decode half now (independent of the match) ----
    {
        float* o = sOut + tid * 18;
        o[5]  = fmaxf(xA - fmaxf(pA.x, 0.0f) * s, 0.0f);
        o[6]  = fmaxf(y  - fmaxf(pA.y, 0.0f) * s, 0.0f);
        o[7]  = fmaxf(xA + fmaxf(pA.z, 0.0f) * s, 0.0f);
        o[8]  = fmaxf(y  + fmaxf(pA.w, 0.0f) * s, 0.0f);
        o[14] = fmaxf(xB - fmaxf(pB.x, 0.0f) * s, 0.0f);
        o[15] = fmaxf(y  - fmaxf(pB.y, 0.0f) * s, 0.0f);
        o[16] = fmaxf(xB + fmaxf(pB.z, 0.0f) * s, 0.0f);
        o[17] = fmaxf(y  + fmaxf(pB.w, 0.0f) * s, 0.0f);
    }

    // ---- Phase 1: 4 warps build compacted per-warp shortlists ----
    {
        // Valid-center window: x in (max(x0,x1-hi), min(x1,x0+hi)), same in y.
        const float xl = fmaxf(bx0, bx1 - hi), xh = fminf(bx1, bx0 + hi);
        const float yl = fmaxf(by0, by1 - hi), yh = fminf(by1, by0 + hi);
        const bool cand = (xh > xl) && (yh > ylo) && (yl < yhi);
        const unsigned mask = __ballot_sync(0xFFFFFFFFu, cand);
        if (cand) {
            const int slot = (w << 5) + __popc(mask & ((1u << lane) - 1u));
            sbox[slot] = make_float4(bx0, by0, bx1, by1);
            const float mmv = 1e8f - (bx1 - bx0) * (by1 - by0);
            // mm bits (positive float, order-isomorphic) | first-index tie | slot.
            skey[slot] = ((unsigned long long)__float_as_uint(mmv) << 32) |
                         ((unsigned)(NGT - 1 - tid) << 8) | (unsigned)slot;
        }
        if (lane == 0) swc[w] = __popc(mask);
    }
    __syncthreads();

    // ---- Phase 2: scan compacted segments, 2 x-positions per entry ----
    unsigned long long bestA = 0ull, bestB = 0ull;
    #pragma unroll
    for (int ws = 0; ws < 4; ++ws) {
        const int cnt  = swc[ws];
        const int base = ws << 5;
        for (int k = 0; k < cnt; ++k) {
            const float4 bx = sbox[base + k];
            const float t  = y - bx.y;
            const float bt = bx.w - y;
            const float vmin = fminf(t, bt);
            const float vmax = fmaxf(t, bt);
            const unsigned long long key = skey[base + k];
            {
                const float l = xA - bx.x, r = bx.z - xA;
                const float pmin = fminf(fminf(l, r), vmin);
                const float pmax = fmaxf(fmaxf(l, r), vmax);
                if (pmin > 0.0f && pmax > lo && pmax < hi && key > bestA)
                    bestA = key;
            }
            {
                const float l = xB - bx.x, r = bx.z - xB;
                const float pmin = fminf(fminf(l, r), vmin);
                const float pmax = fmaxf(fmaxf(l, r), vmax);
                if (pmin > 0.0f && pmax > lo && pmax < hi && key > bestB)
                    bestB = key;
            }
        }
    }

    // ---- Phase 3: stage match outputs (5 floats per location) ----
    {
        const float inv_s = 1.0f / s;
        float* o = sOut + tid * 18;
        #pragma unroll
        for (int q = 0; q < 2; ++q, o += 9) {
            const unsigned long long best = q ? bestB : bestA;
            const float x = q ? xB : xA;
            if (best == 0ull) {
                o[0] = o[1] = o[2] = o[3] = -1.0f;
                o[4] = -1.0f;
            } else {
                const float4 bx = sbox[best & 0xFFu];
                const float d0 = (x - bx.x) * inv_s;
                const float d1 = (y - bx.y) * inv_s;
                const float d2 = (bx.z - x) * inv_s;
                const float d3 = (bx.w - y) * inv_s;
                const float lrmin = fminf(d0, d2), lrmax = fmaxf(d0, d2);
                const float tbmin = fminf(d1, d3), tbmax = fmaxf(d1, d3);
                const float ratio = fminf(lrmin, tbmin) /
                                    (fmaxf(lrmax, tbmax) + 1e-6f);
                o[0] = d0; o[1] = d1; o[2] = d2; o[3] = d3;
                o[4] = sqrtf(fmaxf(ratio, 0.0f));
            }
        }
    }
    __syncwarp();   // warp-local: this warp only copies its own staged region

    // ---- Phase 4: per-warp coalesced copy of its own 576-float region ----
    // Warp region: sOut[576w .. 576(w+1)) -> out[(block base + 64w locs)*9 ..)
    // 144 float4 per warp: 4 full rounds + one half-warp round.
    {
        const float4* src = reinterpret_cast<const float4*>(sOut + 576 * w);
        float4* dst = reinterpret_cast<float4*>(
            out + ((size_t)b * LTOT + off + l0) * 9 + 576 * w);
        #pragma unroll
        for (int k = 0; k < 4; ++k)
            dst[k * 32 + lane] = src[k * 32 + lane];
        if (lane < 16)
            dst[128 + lane] = src[128 + lane];
    }
}

extern "C" void kernel_launch(void* const* d_in, const int* in_sizes, int n_in,
                              void* d_out, int out_size) {
    const float* gt = (const float*)d_in[3];
    const float* p3 = (const float*)d_in[4];
    const float* p4 = (const float*)d_in[5];
    const float* p5 = (const float*)d_in[6];
    float* out = (float*)d_out;

    const int blocks = NB * LTOT / 256;   // 672
    fcos_fused<<<blocks, 128>>>(gt, p3, p4, p5, out);
}